// round 14
// baseline (speedup 1.0000x reference)
#include <cuda_runtime.h>
#include <cuda_bf16.h>
#include <cstdint>

#define BN 64
#define NN 4096
#define MM 128
#define NCH 32
#define CH 128
#define L2E 1.4426950408889634f

// -------- scratch (device globals; zero-initialized at load; no allocations) --------
__device__ float4   g_pack4[BN * NN * 2];          // {el,o0,o1,o2},{o3,o4,o5,0} per (b,n)  (8 MB)
__device__ unsigned g_maxel[BN];                   // bit-key max(el); zero-init = smallest key; atomicMax idempotent
__device__ float4   g_er4[BN * MM / 4];            // er per (b,m)
__device__ float4   g_nb4[BN * MM / 4];            // -boundL*log2(e) per (b,m)
__device__ float    g_kE;                          // dot(w_edge, attn_e)
__device__ float    g_scratch[NCH * BN * 8 * MM];  // partial sums [b][chunk][field][m] (8.4 MB)

__device__ __forceinline__ float ex2f(float x) {
    float y; asm("ex2.approx.ftz.f32 %0, %1;" : "=f"(y) : "f"(x)); return y;
}
__device__ __forceinline__ unsigned fkey(float f) {
    unsigned u = __float_as_uint(f);
    return u ^ ((u >> 31) ? 0xFFFFFFFFu : 0x80000000u);
}
__device__ __forceinline__ float fkeyinv(unsigned k) {
    return __uint_as_float(k ^ ((k & 0x80000000u) ? 0x80000000u : 0xFFFFFFFFu));
}

// -------- kernel 1: coalesced el + pack + per-batch max(el) --------
__global__ __launch_bounds__(256) void k_prep1(
    const float* __restrict__ ope, const float* __restrict__ W_src,
    const float* __restrict__ attn_l, const float* __restrict__ w_edge,
    const float* __restrict__ attn_e)
{
    __shared__ float sraw[1024 * 6];   // 24 KB
    int b = blockIdx.y;
    int n0 = blockIdx.x * 1024;
    int tid = threadIdx.x;

    if (blockIdx.x == 0 && b == 0 && tid == 0) {
        float k = 0.f;
        #pragma unroll
        for (int d = 0; d < 8; d++) k += w_edge[d] * attn_e[d];
        g_kE = k;
    }

    float wsl[6];
    #pragma unroll
    for (int k = 0; k < 6; k++) {
        float s = 0.f;
        #pragma unroll
        for (int d = 0; d < 8; d++) s += __ldg(&W_src[k * 8 + d]) * __ldg(&attn_l[d]);
        wsl[k] = s;
    }

    // coalesced stage: 1536 float4 by 256 threads
    {
        const float4* src = (const float4*)(ope + ((size_t)b * NN + n0) * 6);
        float4* s4 = (float4*)sraw;
        #pragma unroll
        for (int k = 0; k < 6; k++) s4[tid + 256 * k] = src[tid + 256 * k];
    }
    __syncthreads();

    float mymax = -3.4e38f;
    #pragma unroll
    for (int k = 0; k < 4; k++) {
        int r = tid + 256 * k;                 // stride-256 rows: 2-way shared conflicts only
        const float* p = sraw + r * 6;
        float o0 = p[0], o1 = p[1], o2 = p[2], o3 = p[3], o4 = p[4], o5 = p[5];
        float el = o0 * wsl[0] + o1 * wsl[1] + o2 * wsl[2]
                 + o3 * wsl[3] + o4 * wsl[4] + o5 * wsl[5];
        size_t pi = ((size_t)b * NN + n0 + r) * 2;
        g_pack4[pi]     = make_float4(el, o0, o1, o2);
        g_pack4[pi + 1] = make_float4(o3, o4, o5, 0.f);
        mymax = fmaxf(mymax, el);
    }

    float v = mymax;
    #pragma unroll
    for (int off = 16; off; off >>= 1) v = fmaxf(v, __shfl_xor_sync(0xFFFFFFFFu, v, off));
    __shared__ float wm[8];
    if ((tid & 31) == 0) wm[tid >> 5] = v;
    __syncthreads();
    if (tid == 0) {
        float mx = wm[0];
        #pragma unroll
        for (int i = 1; i < 8; i++) mx = fmaxf(mx, wm[i]);
        atomicMax(&g_maxel[b], fkey(mx));
    }
}

// -------- kernel 2: per (b,m): er, safe softmax bound --------
__global__ __launch_bounds__(256) void k_prep2(
    const float* __restrict__ ma, const float* __restrict__ W_dst,
    const float* __restrict__ attn_r)
{
    int i = blockIdx.x * 256 + threadIdx.x;   // 0 .. B*M-1
    if (i >= BN * MM) return;
    int b = i >> 7;

    const float* mp = ma + (size_t)i * 3;
    float m0 = mp[0], m1 = mp[1], m2 = mp[2];
    float er = 0.f;
    #pragma unroll
    for (int d = 0; d < 8; d++) {
        float fd = m0 * W_dst[d] + m1 * W_dst[8 + d] + m2 * W_dst[16 + d];
        er += fd * attn_r[d];
    }
    float kE = g_kE;
    // a = el + er + kE*proc <= maxel + er + max(kE,0) since proc in [0,1]
    float bound = fkeyinv(g_maxel[b]) + er + fmaxf(kE, 0.f);
    float ekk = fmaxf(2.f * er, 0.4f * er);              // leaky(2*er)
    float bl  = fmaxf(fmaxf(bound, 0.2f * bound), ekk);  // max(leaky(bound), ekk)
    ((float*)g_er4)[i] = er;
    ((float*)g_nb4)[i] = -bl * L2E;
}

// -------- kernel 3: main streaming pass over (n, m) -- UNCHANGED (proven ~42us) --------
__global__ __launch_bounds__(256, 2) void k_main(
    const int* __restrict__ adj, const int* __restrict__ bidx,
    const float* __restrict__ proc)
{
    __shared__ float4 sh_pk[CH * 2];        // 4 KB: {el,ope} per n of chunk
    __shared__ float4 sh_part[8][8][32];    // 32 KB: [warp][field][lane] partials

    int b = blockIdx.y, c = blockIdx.x;
    int n0 = c * CH;
    int tid = threadIdx.x;
    int w = tid >> 5, l = tid & 31;        // warp w handles rows nl = w + 8*i; lane l -> m = 4l..4l+3

    int bb = bidx[b];
    const int4*   apw = (const int4*)(adj + ((size_t)bb * NN + n0) * MM) + l + w * 32;
    const float4* ppw = (const float4*)(proc + ((size_t)b * NN + n0) * MM) + l + w * 32;

    // prefetch group 0 (independent of shared)
    int4   Ab[2][4];
    float4 Pb[2][4];
    #pragma unroll
    for (int j = 0; j < 4; j++) {
        Ab[0][j] = __ldcs(apw + j * 256);
        Pb[0][j] = __ldcs(ppw + j * 256);
    }

    {
        const float4* gp = g_pack4 + (size_t)(b * NN + n0) * 2;
        sh_pk[tid] = gp[tid];
    }

    float4 er4 = g_er4[b * 32 + l];
    float4 nb4 = g_nb4[b * 32 + l];
    float  kE  = g_kE;

    float S0 = 0.f, S1 = 0.f, S2 = 0.f, S3 = 0.f;
    float P0 = 0.f, P1 = 0.f, P2 = 0.f, P3 = 0.f;
    float G[4][6];
    #pragma unroll
    for (int j = 0; j < 4; j++)
        #pragma unroll
        for (int k = 0; k < 6; k++) G[j][k] = 0.f;

    __syncthreads();

    #pragma unroll
    for (int g = 0; g < 4; g++) {
        int cur = g & 1;
        if (g < 3) {
            #pragma unroll
            for (int j = 0; j < 4; j++) {
                Ab[cur ^ 1][j] = __ldcs(apw + ((g + 1) * 4 + j) * 256);
                Pb[cur ^ 1][j] = __ldcs(ppw + ((g + 1) * 4 + j) * 256);
            }
        }
        #pragma unroll
        for (int j = 0; j < 4; j++) {
            int nl = (g * 4 + j) * 8 + w;
            float4 k0 = sh_pk[nl * 2];
            float4 k1 = sh_pk[nl * 2 + 1];
            float  el = k0.x;
            int4   a4 = Ab[cur][j];
            float4 p4 = Pb[cur][j];

#define COL(J, AJ, PJ, ERJ, NBJ, SJ, PACC) {                      \
            float a  = fmaf(kE, PJ, ERJ) + el;                    \
            float e  = fmaxf(a, 0.2f * a);                        \
            float wg = (AJ != 0) ? fmaf(e, L2E, NBJ) : -200.f;    \
            float wv = ex2f(wg);                                  \
            SJ += wv;                                             \
            PACC = fmaf(wv, PJ, PACC);                            \
            G[J][0] = fmaf(wv, k0.y, G[J][0]);                    \
            G[J][1] = fmaf(wv, k0.z, G[J][1]);                    \
            G[J][2] = fmaf(wv, k0.w, G[J][2]);                    \
            G[J][3] = fmaf(wv, k1.x, G[J][3]);                    \
            G[J][4] = fmaf(wv, k1.y, G[J][4]);                    \
            G[J][5] = fmaf(wv, k1.z, G[J][5]); }

            COL(0, a4.x, p4.x, er4.x, nb4.x, S0, P0)
            COL(1, a4.y, p4.y, er4.y, nb4.y, S1, P1)
            COL(2, a4.z, p4.z, er4.z, nb4.z, S2, P2)
            COL(3, a4.w, p4.w, er4.w, nb4.w, S3, P3)
#undef COL
        }
    }

    // conflict-free float4 partial writes: [warp][field][lane]
    sh_part[w][0][l] = make_float4(S0, S1, S2, S3);
    sh_part[w][1][l] = make_float4(P0, P1, P2, P3);
    #pragma unroll
    for (int k = 0; k < 6; k++)
        sh_part[w][2 + k][l] = make_float4(G[0][k], G[1][k], G[2][k], G[3][k]);
    __syncthreads();

    // reduce across 8 warps, write chunk partials to scratch
    int m = tid & 127, fh = tid >> 7;
    const float* sp = (const float*)sh_part;
    #pragma unroll
    for (int k = 0; k < 4; k++) {
        int f = fh * 4 + k;
        float s = 0.f;
        #pragma unroll
        for (int ww = 0; ww < 8; ww++) s += sp[ww * 1024 + f * 128 + m];
        g_scratch[(((size_t)b * NCH + c) * 8 + f) * MM + m] = s;
    }
}

// -------- kernel 4: max-parallel chunk reduce + epilogue --------
// grid (16, 64): block = (batch, 8-m group). Thread (f=tid>>5, c=tid&31)
// loads its 8 m-partials as 2 float4 (all 8 KB of block input in flight at
// once), warp-butterfly over lanes (= chunks), 64 threads do the epilogue.
__global__ __launch_bounds__(256) void k_final(
    const float* __restrict__ ma, const float* __restrict__ W_src,
    const float* __restrict__ W_dst, const float* __restrict__ w_edge,
    float* __restrict__ out)
{
    int b = blockIdx.y, mg = blockIdx.x;
    int tid = threadIdx.x;
    int f = tid >> 5, c = tid & 31;
    __shared__ float ssum[8][8];

    const float4* p = (const float4*)(g_scratch
                    + (((size_t)(b * NCH + c)) * 8 + f) * MM + mg * 8);
    float4 v0 = __ldcg(p);
    float4 v1 = __ldcg(p + 1);

    #pragma unroll
    for (int off = 16; off; off >>= 1) {
        v0.x += __shfl_xor_sync(0xFFFFFFFFu, v0.x, off);
        v0.y += __shfl_xor_sync(0xFFFFFFFFu, v0.y, off);
        v0.z += __shfl_xor_sync(0xFFFFFFFFu, v0.z, off);
        v0.w += __shfl_xor_sync(0xFFFFFFFFu, v0.w, off);
        v1.x += __shfl_xor_sync(0xFFFFFFFFu, v1.x, off);
        v1.y += __shfl_xor_sync(0xFFFFFFFFu, v1.y, off);
        v1.z += __shfl_xor_sync(0xFFFFFFFFu, v1.z, off);
        v1.w += __shfl_xor_sync(0xFFFFFFFFu, v1.w, off);
    }
    if (c == 0) {
        ssum[f][0] = v0.x; ssum[f][1] = v0.y; ssum[f][2] = v0.z; ssum[f][3] = v0.w;
        ssum[f][4] = v1.x; ssum[f][5] = v1.y; ssum[f][6] = v1.z; ssum[f][7] = v1.w;
    }
    __syncthreads();

    if (tid < 64) {
        int ms = tid >> 3, d = tid & 7;
        int m = mg * 8 + ms;
        int i = b * MM + m;
        float S  = ssum[0][ms];
        float P  = ssum[1][ms];
        float er = ((const float*)g_er4)[i];
        float nb = ((const float*)g_nb4)[i];
        float ekk = fmaxf(2.f * er, 0.4f * er);
        float wkk = ex2f(fmaf(ekk, L2E, nb));   // same scale as main-pass weights
        float inv = 1.f / (S + wkk);
        const float* mp = ma + (size_t)i * 3;
        float fd = mp[0] * W_dst[d] + mp[1] * W_dst[8 + d] + mp[2] * W_dst[16 + d];
        float gw = 0.f;
        #pragma unroll
        for (int k = 0; k < 6; k++) gw += ssum[2 + k][ms] * W_src[k * 8 + d];
        float val = (P * w_edge[d] + gw + fd * wkk) * inv;
        out[(size_t)i * 8 + d] = 1.f / (1.f + ex2f(-val * L2E));
    }
}

extern "C" void kernel_launch(void* const* d_in, const int* in_sizes, int n_in,
                              void* d_out, int out_size)
{
    const int*   adj    = (const int*)d_in[0];
    const int*   bidx   = (const int*)d_in[1];
    const float* ope    = (const float*)d_in[2];
    const float* ma     = (const float*)d_in[3];
    const float* proc   = (const float*)d_in[4];
    const float* W_src  = (const float*)d_in[5];
    const float* W_dst  = (const float*)d_in[6];
    const float* w_edge = (const float*)d_in[7];
    const float* attn_l = (const float*)d_in[8];
    const float* attn_r = (const float*)d_in[9];
    const float* attn_e = (const float*)d_in[10];
    float* out = (float*)d_out;

    k_prep1<<<dim3(4, 64), 256>>>(ope, W_src, attn_l, w_edge, attn_e);
    k_prep2<<<32, 256>>>(ma, W_dst, attn_r);
    k_main <<<dim3(NCH, 64), 256>>>(adj, bidx, proc);
    k_final<<<dim3(16, 64), 256>>>(ma, W_src, W_dst, w_edge, out);
}

// round 15
// speedup vs baseline: 1.0556x; 1.0556x over previous
#include <cuda_runtime.h>
#include <cuda_bf16.h>
#include <cstdint>

#define BN 64
#define NN 4096
#define MM 128
#define NCH 32
#define CH 128
#define L2E 1.4426950408889634f

// -------- scratch (device globals; zero-initialized at load; no allocations) --------
__device__ float4   g_pack4[BN * NN * 2];          // {el,o0,o1,o2},{o3,o4,o5,0} per (b,n)  (8 MB)
__device__ unsigned g_maxel[BN];                   // bit-key max(el); zero-init = smallest key; atomicMax idempotent
__device__ float4   g_er4[BN * MM / 4];            // er per (b,m)
__device__ float4   g_nb4[BN * MM / 4];            // -boundL*log2(e) per (b,m)
__device__ float    g_kE;                          // dot(w_edge, attn_e)
__device__ float    g_scratch[NCH * BN * 8 * MM];  // partial sums [b][chunk][field][m] (8.4 MB)

__device__ __forceinline__ float ex2f(float x) {
    float y; asm("ex2.approx.ftz.f32 %0, %1;" : "=f"(y) : "f"(x)); return y;
}
__device__ __forceinline__ unsigned fkey(float f) {
    unsigned u = __float_as_uint(f);
    return u ^ ((u >> 31) ? 0xFFFFFFFFu : 0x80000000u);
}
__device__ __forceinline__ float fkeyinv(unsigned k) {
    return __uint_as_float(k ^ ((k & 0x80000000u) ? 0x80000000u : 0xFFFFFFFFu));
}

// -------- kernel 1: coalesced el + pack + per-batch max(el) --------
__global__ __launch_bounds__(256) void k_prep1(
    const float* __restrict__ ope, const float* __restrict__ W_src,
    const float* __restrict__ attn_l, const float* __restrict__ w_edge,
    const float* __restrict__ attn_e)
{
    __shared__ float sraw[1024 * 6];   // 24 KB
    int b = blockIdx.y;
    int n0 = blockIdx.x * 1024;
    int tid = threadIdx.x;

    if (blockIdx.x == 0 && b == 0 && tid == 0) {
        float k = 0.f;
        #pragma unroll
        for (int d = 0; d < 8; d++) k += w_edge[d] * attn_e[d];
        g_kE = k;
    }

    float wsl[6];
    #pragma unroll
    for (int k = 0; k < 6; k++) {
        float s = 0.f;
        #pragma unroll
        for (int d = 0; d < 8; d++) s += __ldg(&W_src[k * 8 + d]) * __ldg(&attn_l[d]);
        wsl[k] = s;
    }

    // coalesced stage: 1536 float4 by 256 threads
    {
        const float4* src = (const float4*)(ope + ((size_t)b * NN + n0) * 6);
        float4* s4 = (float4*)sraw;
        #pragma unroll
        for (int k = 0; k < 6; k++) s4[tid + 256 * k] = src[tid + 256 * k];
    }
    __syncthreads();

    float mymax = -3.4e38f;
    #pragma unroll
    for (int k = 0; k < 4; k++) {
        int r = tid + 256 * k;                 // stride-256 rows: 2-way shared conflicts only
        const float* p = sraw + r * 6;
        float o0 = p[0], o1 = p[1], o2 = p[2], o3 = p[3], o4 = p[4], o5 = p[5];
        float el = o0 * wsl[0] + o1 * wsl[1] + o2 * wsl[2]
                 + o3 * wsl[3] + o4 * wsl[4] + o5 * wsl[5];
        size_t pi = ((size_t)b * NN + n0 + r) * 2;
        g_pack4[pi]     = make_float4(el, o0, o1, o2);
        g_pack4[pi + 1] = make_float4(o3, o4, o5, 0.f);
        mymax = fmaxf(mymax, el);
    }

    float v = mymax;
    #pragma unroll
    for (int off = 16; off; off >>= 1) v = fmaxf(v, __shfl_xor_sync(0xFFFFFFFFu, v, off));
    __shared__ float wm[8];
    if ((tid & 31) == 0) wm[tid >> 5] = v;
    __syncthreads();
    if (tid == 0) {
        float mx = wm[0];
        #pragma unroll
        for (int i = 1; i < 8; i++) mx = fmaxf(mx, wm[i]);
        atomicMax(&g_maxel[b], fkey(mx));
    }
}

// -------- kernel 2: per (b,m): er, safe softmax bound --------
__global__ __launch_bounds__(256) void k_prep2(
    const float* __restrict__ ma, const float* __restrict__ W_dst,
    const float* __restrict__ attn_r)
{
    int i = blockIdx.x * 256 + threadIdx.x;   // 0 .. B*M-1
    if (i >= BN * MM) return;
    int b = i >> 7;

    const float* mp = ma + (size_t)i * 3;
    float m0 = mp[0], m1 = mp[1], m2 = mp[2];
    float er = 0.f;
    #pragma unroll
    for (int d = 0; d < 8; d++) {
        float fd = m0 * W_dst[d] + m1 * W_dst[8 + d] + m2 * W_dst[16 + d];
        er += fd * attn_r[d];
    }
    float kE = g_kE;
    // a = el + er + kE*proc <= maxel + er + max(kE,0) since proc in [0,1]
    float bound = fkeyinv(g_maxel[b]) + er + fmaxf(kE, 0.f);
    float ekk = fmaxf(2.f * er, 0.4f * er);              // leaky(2*er)
    float bl  = fmaxf(fmaxf(bound, 0.2f * bound), ekk);  // max(leaky(bound), ekk)
    ((float*)g_er4)[i] = er;
    ((float*)g_nb4)[i] = -bl * L2E;
}

// -------- kernel 3: main streaming pass over (n, m) -- UNCHANGED (proven ~42us) --------
__global__ __launch_bounds__(256, 2) void k_main(
    const int* __restrict__ adj, const int* __restrict__ bidx,
    const float* __restrict__ proc)
{
    __shared__ float4 sh_pk[CH * 2];        // 4 KB: {el,ope} per n of chunk
    __shared__ float4 sh_part[8][8][32];    // 32 KB: [warp][field][lane] partials

    int b = blockIdx.y, c = blockIdx.x;
    int n0 = c * CH;
    int tid = threadIdx.x;
    int w = tid >> 5, l = tid & 31;        // warp w handles rows nl = w + 8*i; lane l -> m = 4l..4l+3

    int bb = bidx[b];
    const int4*   apw = (const int4*)(adj + ((size_t)bb * NN + n0) * MM) + l + w * 32;
    const float4* ppw = (const float4*)(proc + ((size_t)b * NN + n0) * MM) + l + w * 32;

    // prefetch group 0 (independent of shared)
    int4   Ab[2][4];
    float4 Pb[2][4];
    #pragma unroll
    for (int j = 0; j < 4; j++) {
        Ab[0][j] = __ldcs(apw + j * 256);
        Pb[0][j] = __ldcs(ppw + j * 256);
    }

    {
        const float4* gp = g_pack4 + (size_t)(b * NN + n0) * 2;
        sh_pk[tid] = gp[tid];
    }

    float4 er4 = g_er4[b * 32 + l];
    float4 nb4 = g_nb4[b * 32 + l];
    float  kE  = g_kE;

    float S0 = 0.f, S1 = 0.f, S2 = 0.f, S3 = 0.f;
    float P0 = 0.f, P1 = 0.f, P2 = 0.f, P3 = 0.f;
    float G[4][6];
    #pragma unroll
    for (int j = 0; j < 4; j++)
        #pragma unroll
        for (int k = 0; k < 6; k++) G[j][k] = 0.f;

    __syncthreads();

    #pragma unroll
    for (int g = 0; g < 4; g++) {
        int cur = g & 1;
        if (g < 3) {
            #pragma unroll
            for (int j = 0; j < 4; j++) {
                Ab[cur ^ 1][j] = __ldcs(apw + ((g + 1) * 4 + j) * 256);
                Pb[cur ^ 1][j] = __ldcs(ppw + ((g + 1) * 4 + j) * 256);
            }
        }
        #pragma unroll
        for (int j = 0; j < 4; j++) {
            int nl = (g * 4 + j) * 8 + w;
            float4 k0 = sh_pk[nl * 2];
            float4 k1 = sh_pk[nl * 2 + 1];
            float  el = k0.x;
            int4   a4 = Ab[cur][j];
            float4 p4 = Pb[cur][j];

#define COL(J, AJ, PJ, ERJ, NBJ, SJ, PACC) {                      \
            float a  = fmaf(kE, PJ, ERJ) + el;                    \
            float e  = fmaxf(a, 0.2f * a);                        \
            float wg = (AJ != 0) ? fmaf(e, L2E, NBJ) : -200.f;    \
            float wv = ex2f(wg);                                  \
            SJ += wv;                                             \
            PACC = fmaf(wv, PJ, PACC);                            \
            G[J][0] = fmaf(wv, k0.y, G[J][0]);                    \
            G[J][1] = fmaf(wv, k0.z, G[J][1]);                    \
            G[J][2] = fmaf(wv, k0.w, G[J][2]);                    \
            G[J][3] = fmaf(wv, k1.x, G[J][3]);                    \
            G[J][4] = fmaf(wv, k1.y, G[J][4]);                    \
            G[J][5] = fmaf(wv, k1.z, G[J][5]); }

            COL(0, a4.x, p4.x, er4.x, nb4.x, S0, P0)
            COL(1, a4.y, p4.y, er4.y, nb4.y, S1, P1)
            COL(2, a4.z, p4.z, er4.z, nb4.z, S2, P2)
            COL(3, a4.w, p4.w, er4.w, nb4.w, S3, P3)
#undef COL
        }
    }

    // conflict-free float4 partial writes: [warp][field][lane]
    sh_part[w][0][l] = make_float4(S0, S1, S2, S3);
    sh_part[w][1][l] = make_float4(P0, P1, P2, P3);
    #pragma unroll
    for (int k = 0; k < 6; k++)
        sh_part[w][2 + k][l] = make_float4(G[0][k], G[1][k], G[2][k], G[3][k]);
    __syncthreads();

    // reduce across 8 warps, write chunk partials to scratch
    int m = tid & 127, fh = tid >> 7;
    const float* sp = (const float*)sh_part;
    #pragma unroll
    for (int k = 0; k < 4; k++) {
        int f = fh * 4 + k;
        float s = 0.f;
        #pragma unroll
        for (int ww = 0; ww < 8; ww++) s += sp[ww * 1024 + f * 128 + m];
        g_scratch[(((size_t)b * NCH + c) * 8 + f) * MM + m] = s;
    }
}

// -------- kernel 4: coalesced + full-MLP chunk reduce + epilogue --------
// grid (4, 64): block = (batch, 32-m quarter). Warp w owns field w, lane l
// owns m = q*32+l. Each lane loads 32 chunk-partials (128B coalesced per
// warp-load, 32 independent loads in flight), tree-sums, then 256 threads
// produce the block's 256 outputs (one each).
__global__ __launch_bounds__(256) void k_final(
    const float* __restrict__ ma, const float* __restrict__ W_src,
    const float* __restrict__ W_dst, const float* __restrict__ w_edge,
    float* __restrict__ out)
{
    int b = blockIdx.y, q = blockIdx.x;
    int tid = threadIdx.x, w = tid >> 5, l = tid & 31;
    __shared__ float ssum[8][32];

    const float* base = g_scratch + (((size_t)b * NCH) * 8 + w) * MM + q * 32 + l;
    float v[NCH];
    #pragma unroll
    for (int c = 0; c < NCH; c++) v[c] = __ldcg(base + (size_t)c * 8 * MM);
    // pairwise tree sum (keeps loads independent of adds)
    #pragma unroll
    for (int st = 1; st < NCH; st <<= 1)
        #pragma unroll
        for (int c = 0; c < NCH; c += 2 * st) v[c] += v[c + st];
    ssum[w][l] = v[0];
    __syncthreads();

    int ms = tid >> 3, d = tid & 7;        // 32 m x 8 d = 256 outputs
    int m = q * 32 + ms;
    int i = b * MM + m;
    float S  = ssum[0][ms];
    float P  = ssum[1][ms];
    float er = ((const float*)g_er4)[i];
    float nb = ((const float*)g_nb4)[i];
    float ekk = fmaxf(2.f * er, 0.4f * er);
    float wkk = ex2f(fmaf(ekk, L2E, nb));   // same scale as main-pass weights
    float inv = 1.f / (S + wkk);
    const float* mp = ma + (size_t)i * 3;
    float fd = mp[0] * W_dst[d] + mp[1] * W_dst[8 + d] + mp[2] * W_dst[16 + d];
    float gw = 0.f;
    #pragma unroll
    for (int k = 0; k < 6; k++) gw += ssum[2 + k][ms] * W_src[k * 8 + d];
    float val = (P * w_edge[d] + gw + fd * wkk) * inv;
    out[(size_t)i * 8 + d] = 1.f / (1.f + ex2f(-val * L2E));
}

extern "C" void kernel_launch(void* const* d_in, const int* in_sizes, int n_in,
                              void* d_out, int out_size)
{
    const int*   adj    = (const int*)d_in[0];
    const int*   bidx   = (const int*)d_in[1];
    const float* ope    = (const float*)d_in[2];
    const float* ma     = (const float*)d_in[3];
    const float* proc   = (const float*)d_in[4];
    const float* W_src  = (const float*)d_in[5];
    const float* W_dst  = (const float*)d_in[6];
    const float* w_edge = (const float*)d_in[7];
    const float* attn_l = (const float*)d_in[8];
    const float* attn_r = (const float*)d_in[9];
    const float* attn_e = (const float*)d_in[10];
    float* out = (float*)d_out;

    k_prep1<<<dim3(4, 64), 256>>>(ope, W_src, attn_l, w_edge, attn_e);
    k_prep2<<<32, 256>>>(ma, W_dst, attn_r);
    k_main <<<dim3(NCH, 64), 256>>>(adj, bidx, proc);
    k_final<<<dim3(4, 64), 256>>>(ma, W_src, W_dst, w_edge, out);
}

// round 16
// speedup vs baseline: 1.0826x; 1.0256x over previous
#include <cuda_runtime.h>
#include <cuda_bf16.h>
#include <cstdint>

#define BN 64
#define NN 4096
#define MM 128
#define NCH 32
#define CH 128
#define L2E 1.4426950408889634f

// -------- scratch (device globals; zero-initialized at load; no allocations) --------
__device__ float4   g_pack4[BN * NN * 2];          // {el,o0,o1,o2},{o3,o4,o5,0} per (b,n)  (8 MB)
__device__ unsigned g_maxel[BN];                   // bit-key max(el); zero-init = smallest key; atomicMax idempotent
__device__ float4   g_er4[BN * MM / 4];            // er per (b,m)
__device__ float4   g_nb4[BN * MM / 4];            // -boundL*log2(e) per (b,m)
__device__ float    g_kE;                          // dot(w_edge, attn_e)
__device__ float    g_acc[BN * 8 * MM];            // final sums [b][field][m] (256 KB, L2-resident)

__device__ __forceinline__ float ex2f(float x) {
    float y; asm("ex2.approx.ftz.f32 %0, %1;" : "=f"(y) : "f"(x)); return y;
}
__device__ __forceinline__ unsigned fkey(float f) {
    unsigned u = __float_as_uint(f);
    return u ^ ((u >> 31) ? 0xFFFFFFFFu : 0x80000000u);
}
__device__ __forceinline__ float fkeyinv(unsigned k) {
    return __uint_as_float(k ^ ((k & 0x80000000u) ? 0x80000000u : 0xFFFFFFFFu));
}

// -------- kernel 1: coalesced el + pack + per-batch max(el) + acc zeroing --------
__global__ __launch_bounds__(256) void k_prep1(
    const float* __restrict__ ope, const float* __restrict__ W_src,
    const float* __restrict__ attn_l, const float* __restrict__ w_edge,
    const float* __restrict__ attn_e)
{
    __shared__ float sraw[1024 * 6];   // 24 KB
    int b = blockIdx.y;
    int n0 = blockIdx.x * 1024;
    int tid = threadIdx.x;

    // zero the accumulator for this run (256 blocks x 256 threads = 65536 = BN*8*MM)
    g_acc[(b * 4 + blockIdx.x) * 256 + tid] = 0.f;

    if (blockIdx.x == 0 && b == 0 && tid == 0) {
        float k = 0.f;
        #pragma unroll
        for (int d = 0; d < 8; d++) k += w_edge[d] * attn_e[d];
        g_kE = k;
    }

    float wsl[6];
    #pragma unroll
    for (int k = 0; k < 6; k++) {
        float s = 0.f;
        #pragma unroll
        for (int d = 0; d < 8; d++) s += __ldg(&W_src[k * 8 + d]) * __ldg(&attn_l[d]);
        wsl[k] = s;
    }

    // coalesced stage: 1536 float4 by 256 threads
    {
        const float4* src = (const float4*)(ope + ((size_t)b * NN + n0) * 6);
        float4* s4 = (float4*)sraw;
        #pragma unroll
        for (int k = 0; k < 6; k++) s4[tid + 256 * k] = src[tid + 256 * k];
    }
    __syncthreads();

    float mymax = -3.4e38f;
    #pragma unroll
    for (int k = 0; k < 4; k++) {
        int r = tid + 256 * k;                 // stride-256 rows: 2-way shared conflicts only
        const float* p = sraw + r * 6;
        float o0 = p[0], o1 = p[1], o2 = p[2], o3 = p[3], o4 = p[4], o5 = p[5];
        float el = o0 * wsl[0] + o1 * wsl[1] + o2 * wsl[2]
                 + o3 * wsl[3] + o4 * wsl[4] + o5 * wsl[5];
        size_t pi = ((size_t)b * NN + n0 + r) * 2;
        g_pack4[pi]     = make_float4(el, o0, o1, o2);
        g_pack4[pi + 1] = make_float4(o3, o4, o5, 0.f);
        mymax = fmaxf(mymax, el);
    }

    float v = mymax;
    #pragma unroll
    for (int off = 16; off; off >>= 1) v = fmaxf(v, __shfl_xor_sync(0xFFFFFFFFu, v, off));
    __shared__ float wm[8];
    if ((tid & 31) == 0) wm[tid >> 5] = v;
    __syncthreads();
    if (tid == 0) {
        float mx = wm[0];
        #pragma unroll
        for (int i = 1; i < 8; i++) mx = fmaxf(mx, wm[i]);
        atomicMax(&g_maxel[b], fkey(mx));
    }
}

// -------- kernel 2: per (b,m): er, safe softmax bound --------
__global__ __launch_bounds__(256) void k_prep2(
    const float* __restrict__ ma, const float* __restrict__ W_dst,
    const float* __restrict__ attn_r)
{
    int i = blockIdx.x * 256 + threadIdx.x;   // 0 .. B*M-1
    if (i >= BN * MM) return;
    int b = i >> 7;

    const float* mp = ma + (size_t)i * 3;
    float m0 = mp[0], m1 = mp[1], m2 = mp[2];
    float er = 0.f;
    #pragma unroll
    for (int d = 0; d < 8; d++) {
        float fd = m0 * W_dst[d] + m1 * W_dst[8 + d] + m2 * W_dst[16 + d];
        er += fd * attn_r[d];
    }
    float kE = g_kE;
    // a = el + er + kE*proc <= maxel + er + max(kE,0) since proc in [0,1]
    float bound = fkeyinv(g_maxel[b]) + er + fmaxf(kE, 0.f);
    float ekk = fmaxf(2.f * er, 0.4f * er);              // leaky(2*er)
    float bl  = fmaxf(fmaxf(bound, 0.2f * bound), ekk);  // max(leaky(bound), ekk)
    ((float*)g_er4)[i] = er;
    ((float*)g_nb4)[i] = -bl * L2E;
}

// -------- kernel 3: main streaming pass; REDG-accumulate into g_acc --------
__global__ __launch_bounds__(256, 2) void k_main(
    const int* __restrict__ adj, const int* __restrict__ bidx,
    const float* __restrict__ proc)
{
    __shared__ float4 sh_pk[CH * 2];        // 4 KB: {el,ope} per n of chunk
    __shared__ float4 sh_part[8][8][32];    // 32 KB: [warp][field][lane] partials

    int b = blockIdx.y, c = blockIdx.x;
    int n0 = c * CH;
    int tid = threadIdx.x;
    int w = tid >> 5, l = tid & 31;        // warp w handles rows nl = w + 8*i; lane l -> m = 4l..4l+3

    int bb = bidx[b];
    const int4*   apw = (const int4*)(adj + ((size_t)bb * NN + n0) * MM) + l + w * 32;
    const float4* ppw = (const float4*)(proc + ((size_t)b * NN + n0) * MM) + l + w * 32;

    // prefetch group 0 (independent of shared)
    int4   Ab[2][4];
    float4 Pb[2][4];
    #pragma unroll
    for (int j = 0; j < 4; j++) {
        Ab[0][j] = __ldcs(apw + j * 256);
        Pb[0][j] = __ldcs(ppw + j * 256);
    }

    {
        const float4* gp = g_pack4 + (size_t)(b * NN + n0) * 2;
        sh_pk[tid] = gp[tid];
    }

    float4 er4 = g_er4[b * 32 + l];
    float4 nb4 = g_nb4[b * 32 + l];
    float  kE  = g_kE;

    float S0 = 0.f, S1 = 0.f, S2 = 0.f, S3 = 0.f;
    float P0 = 0.f, P1 = 0.f, P2 = 0.f, P3 = 0.f;
    float G[4][6];
    #pragma unroll
    for (int j = 0; j < 4; j++)
        #pragma unroll
        for (int k = 0; k < 6; k++) G[j][k] = 0.f;

    __syncthreads();

    #pragma unroll
    for (int g = 0; g < 4; g++) {
        int cur = g & 1;
        if (g < 3) {
            #pragma unroll
            for (int j = 0; j < 4; j++) {
                Ab[cur ^ 1][j] = __ldcs(apw + ((g + 1) * 4 + j) * 256);
                Pb[cur ^ 1][j] = __ldcs(ppw + ((g + 1) * 4 + j) * 256);
            }
        }
        #pragma unroll
        for (int j = 0; j < 4; j++) {
            int nl = (g * 4 + j) * 8 + w;
            float4 k0 = sh_pk[nl * 2];
            float4 k1 = sh_pk[nl * 2 + 1];
            float  el = k0.x;
            int4   a4 = Ab[cur][j];
            float4 p4 = Pb[cur][j];

#define COL(J, AJ, PJ, ERJ, NBJ, SJ, PACC) {                      \
            float a  = fmaf(kE, PJ, ERJ) + el;                    \
            float e  = fmaxf(a, 0.2f * a);                        \
            float wg = (AJ != 0) ? fmaf(e, L2E, NBJ) : -200.f;    \
            float wv = ex2f(wg);                                  \
            SJ += wv;                                             \
            PACC = fmaf(wv, PJ, PACC);                            \
            G[J][0] = fmaf(wv, k0.y, G[J][0]);                    \
            G[J][1] = fmaf(wv, k0.z, G[J][1]);                    \
            G[J][2] = fmaf(wv, k0.w, G[J][2]);                    \
            G[J][3] = fmaf(wv, k1.x, G[J][3]);                    \
            G[J][4] = fmaf(wv, k1.y, G[J][4]);                    \
            G[J][5] = fmaf(wv, k1.z, G[J][5]); }

            COL(0, a4.x, p4.x, er4.x, nb4.x, S0, P0)
            COL(1, a4.y, p4.y, er4.y, nb4.y, S1, P1)
            COL(2, a4.z, p4.z, er4.z, nb4.z, S2, P2)
            COL(3, a4.w, p4.w, er4.w, nb4.w, S3, P3)
#undef COL
        }
    }

    // conflict-free float4 partial writes: [warp][field][lane]
    sh_part[w][0][l] = make_float4(S0, S1, S2, S3);
    sh_part[w][1][l] = make_float4(P0, P1, P2, P3);
    #pragma unroll
    for (int k = 0; k < 6; k++)
        sh_part[w][2 + k][l] = make_float4(G[0][k], G[1][k], G[2][k], G[3][k]);
    __syncthreads();

    // reduce across 8 warps, REDG-accumulate into the 256KB L2-hot table
    int m = tid & 127, fh = tid >> 7;
    const float* sp = (const float*)sh_part;
    #pragma unroll
    for (int k = 0; k < 4; k++) {
        int f = fh * 4 + k;
        float s = 0.f;
        #pragma unroll
        for (int ww = 0; ww < 8; ww++) s += sp[ww * 1024 + f * 128 + m];
        atomicAdd(&g_acc[((size_t)b * 8 + f) * MM + m], s);
    }
}

// -------- kernel 4: tiny epilogue over the L2-hot accumulator --------
// grid (4, 64): block = (batch, 32-m quarter); one shared stage read + one
// output per thread.
__global__ __launch_bounds__(256) void k_final(
    const float* __restrict__ ma, const float* __restrict__ W_src,
    const float* __restrict__ W_dst, const float* __restrict__ w_edge,
    float* __restrict__ out)
{
    int b = blockIdx.y, q = blockIdx.x;
    int tid = threadIdx.x, f = tid >> 5, l = tid & 31;
    __shared__ float ssum[8][32];

    ssum[f][l] = __ldcg(&g_acc[((size_t)b * 8 + f) * MM + q * 32 + l]);
    __syncthreads();

    int ms = tid >> 3, d = tid & 7;        // 32 m x 8 d = 256 outputs
    int m = q * 32 + ms;
    int i = b * MM + m;
    float S  = ssum[0][ms];
    float P  = ssum[1][ms];
    float er = ((const float*)g_er4)[i];
    float nb = ((const float*)g_nb4)[i];
    float ekk = fmaxf(2.f * er, 0.4f * er);
    float wkk = ex2f(fmaf(ekk, L2E, nb));   // same scale as main-pass weights
    float inv = 1.f / (S + wkk);
    const float* mp = ma + (size_t)i * 3;
    float fd = mp[0] * W_dst[d] + mp[1] * W_dst[8 + d] + mp[2] * W_dst[16 + d];
    float gw = 0.f;
    #pragma unroll
    for (int k = 0; k < 6; k++) gw += ssum[2 + k][ms] * W_src[k * 8 + d];
    float val = (P * w_edge[d] + gw + fd * wkk) * inv;
    out[(size_t)i * 8 + d] = 1.f / (1.f + ex2f(-val * L2E));
}

extern "C" void kernel_launch(void* const* d_in, const int* in_sizes, int n_in,
                              void* d_out, int out_size)
{
    const int*   adj    = (const int*)d_in[0];
    const int*   bidx   = (const int*)d_in[1];
    const float* ope    = (const float*)d_in[2];
    const float* ma     = (const float*)d_in[3];
    const float* proc   = (const float*)d_in[4];
    const float* W_src  = (const float*)d_in[5];
    const float* W_dst  = (const float*)d_in[6];
    const float* w_edge = (const float*)d_in[7];
    const float* attn_l = (const float*)d_in[8];
    const float* attn_r = (const float*)d_in[9];
    const float* attn_e = (const float*)d_in[10];
    float* out = (float*)d_out;

    k_prep1<<<dim3(4, 64), 256>>>(ope, W_src, attn_l, w_edge, attn_e);
    k_prep2<<<32, 256>>>(ma, W_dst, attn_r);
    k_main <<<dim3(NCH, 64), 256>>>(adj, bidx, proc);
    k_final<<<dim3(4, 64), 256>>>(ma, W_src, W_dst, w_edge, out);
}